// round 2
// baseline (speedup 1.0000x reference)
#include <cuda_runtime.h>

// Problem constants
#define B_DIM 8192
#define D_DIM 2048
#define M_DIM 8
#define C_DIM 1000
#define N_DIM 8000   // M*C

// Tiling
#define BM 128
#define BN 64
#define BK 16
#define TM 8
#define TN 8
#define NTHREADS 128   // (BM/TM)*(BN/TN) = 16*8

// 256 MB scratch for per-(b, m, c) products (device global: no runtime alloc)
__device__ float g_prod[(size_t)B_DIM * N_DIM];

// Fused dual-GEMM: acc1 = x @ Wt (Wt[k, m*C+c] = model_weights[m,k,c]),
//                  acc2 = x @ R.
// Epilogue: g_prod[b, n] = (acc1 + mb[n]) * (acc2 + rb[n]).
__global__ __launch_bounds__(NTHREADS) void fused_dual_gemm(
    const float* __restrict__ x,    // [B, D]
    const float* __restrict__ mw,   // [M, D, C]
    const float* __restrict__ mb,   // [M, C]
    const float* __restrict__ rw,   // [D, N]
    const float* __restrict__ rb)   // [N]
{
    __shared__ float As[BK][BM + 4];   // transposed x tile, padded (stride 132)
    __shared__ float Bs1[BK][BN];      // Wt tile
    __shared__ float Bs2[BK][BN];      // R tile

    const int bn  = blockIdx.x * BN;
    const int bm  = blockIdx.y * BM;
    const int tid = threadIdx.x;
    const int tx  = tid & 7;    // col group: cols tx*8 .. tx*8+7
    const int ty  = tid >> 3;   // row group: rows ty*8 .. ty*8+7

    // Precompute gather offsets for the Wt tile (1024 scalars / 128 threads = 8 each).
    // Element e: row = e>>6 (k within tile), col = e&63; n = bn+col; m = n/C; c = n%C.
    int w_off[8];
#pragma unroll
    for (int i = 0; i < 8; i++) {
        int e   = tid + NTHREADS * i;
        int row = e >> 6;
        int col = e & 63;
        int n   = bn + col;
        int m   = n / C_DIM;
        int c   = n - m * C_DIM;
        w_off[i] = m * (D_DIM * C_DIM) + row * C_DIM + c;
    }

    float acc1[TM][TN];
    float acc2[TM][TN];
#pragma unroll
    for (int i = 0; i < TM; i++)
#pragma unroll
        for (int j = 0; j < TN; j++) { acc1[i][j] = 0.0f; acc2[i][j] = 0.0f; }

    for (int k0 = 0; k0 < D_DIM; k0 += BK) {
        // ---- Load As: 128 rows x 16 k = 512 float4; 4 per thread ----
#pragma unroll
        for (int i = 0; i < 4; i++) {
            int e4  = tid + NTHREADS * i;
            int row = e4 >> 2;            // 0..127
            int kq  = (e4 & 3) * 4;       // 0,4,8,12
            float4 v = *(const float4*)(x + (size_t)(bm + row) * D_DIM + k0 + kq);
            As[kq + 0][row] = v.x;
            As[kq + 1][row] = v.y;
            As[kq + 2][row] = v.z;
            As[kq + 3][row] = v.w;
        }
        // ---- Load Bs2 (resnet_weight): 16 rows x 64 cols = 256 float4; 2 per thread ----
#pragma unroll
        for (int i = 0; i < 2; i++) {
            int e4  = tid + NTHREADS * i;
            int row = e4 >> 4;            // 0..15
            int cq  = (e4 & 15) * 4;      // 0..60
            *(float4*)&Bs2[row][cq] =
                *(const float4*)(rw + (size_t)(k0 + row) * N_DIM + bn + cq);
        }
        // ---- Load Bs1 (gathered model_weights): 1024 scalars; 8 per thread ----
        {
            const int kadd = k0 * C_DIM;
#pragma unroll
            for (int i = 0; i < 8; i++) {
                int e   = tid + NTHREADS * i;
                int row = e >> 6;
                int col = e & 63;
                Bs1[row][col] = mw[w_off[i] + kadd];
            }
        }
        __syncthreads();

        // ---- Compute: 16 k-steps, 128 FMA each ----
#pragma unroll
        for (int k = 0; k < BK; k++) {
            float a[TM], b1[TN], b2[TN];
            *(float4*)&a[0]  = *(const float4*)&As[k][ty * TM];
            *(float4*)&a[4]  = *(const float4*)&As[k][ty * TM + 4];
            *(float4*)&b1[0] = *(const float4*)&Bs1[k][tx * TN];
            *(float4*)&b1[4] = *(const float4*)&Bs1[k][tx * TN + 4];
            *(float4*)&b2[0] = *(const float4*)&Bs2[k][tx * TN];
            *(float4*)&b2[4] = *(const float4*)&Bs2[k][tx * TN + 4];
#pragma unroll
            for (int i = 0; i < TM; i++) {
#pragma unroll
                for (int j = 0; j < TN; j++) {
                    acc1[i][j] = fmaf(a[i], b1[j], acc1[i][j]);
                    acc2[i][j] = fmaf(a[i], b2[j], acc2[i][j]);
                }
            }
        }
        __syncthreads();
    }

    // ---- Epilogue: biases, product, write to scratch ----
#pragma unroll
    for (int j = 0; j < TN; j++) {
        int n = bn + tx * TN + j;
        int m = n / C_DIM;
        int c = n - m * C_DIM;
        float bias1 = mb[m * C_DIM + c];
        float bias2 = rb[n];
#pragma unroll
        for (int i = 0; i < TM; i++) {
            int row = bm + ty * TM + i;
            g_prod[(size_t)row * N_DIM + n] =
                (acc1[i][j] + bias1) * (acc2[i][j] + bias2);
        }
    }
}

// out[b, c] = sum_m g_prod[b, m*C + c]
__global__ __launch_bounds__(256) void reduce_over_m(float* __restrict__ out)
{
    int idx = blockIdx.x * blockDim.x + threadIdx.x;
    if (idx >= B_DIM * C_DIM) return;
    int b = idx / C_DIM;
    int c = idx - b * C_DIM;
    const float* p = g_prod + (size_t)b * N_DIM + c;
    float s = 0.0f;
#pragma unroll
    for (int m = 0; m < M_DIM; m++) s += p[m * C_DIM];
    out[idx] = s;
}

extern "C" void kernel_launch(void* const* d_in, const int* in_sizes, int n_in,
                              void* d_out, int out_size)
{
    const float* x  = (const float*)d_in[0];   // [8192, 2048]
    const float* mw = (const float*)d_in[1];   // [8, 2048, 1000]
    const float* mb = (const float*)d_in[2];   // [8, 1000]
    const float* rw = (const float*)d_in[3];   // [2048, 8000]
    const float* rb = (const float*)d_in[4];   // [8000]
    float* out = (float*)d_out;                // [8192, 1000]

    dim3 grid(N_DIM / BN, B_DIM / BM);         // 125 x 64
    fused_dual_gemm<<<grid, NTHREADS>>>(x, mw, mb, rw, rb);

    int total = B_DIM * C_DIM;
    reduce_over_m<<<(total + 255) / 256, 256>>>(out);
}

// round 7
// speedup vs baseline: 1.6479x; 1.6479x over previous
#include <cuda_runtime.h>
#include <cstdint>

// ---------------------------------------------------------------------------
// out[b,c] = sum_m (x@mw[m] + mb[m])[b,c] * (x@rw + rb)[b, m*1000+c]
//   B=8192, D=2048, M=8, C=1000
// Plan: P[8192,16384] = X @ [ mw^T | rw ]  (C padded 1000->1024), computed as
// 3xTF32 (hi*hi + hi*lo + lo*hi) with mma.sync.m16n8k8 (plain sm_100-legal),
// operands pre-packed in fragment layout; then a combine kernel does
// bias + product + reduce over m.
// ---------------------------------------------------------------------------

#define B_DIM 8192
#define D_DIM 2048
#define C_DIM 1000
#define M_DIM 8
#define NH    8192
#define NP    16384
#define KB_TOT (D_DIM / 8)        // 256 k-blocks of 8

// GEMM tiling
#define TILE_MM 128
#define TILE_NN 128
#define TILE_KK 32
#define KITERS (D_DIM / TILE_KK)  // 64
#define NSTAGES 3
#define NTHREADS 256

#define A_SZ 16384                 // 128 rows * 32 k * 4B (one of hi/lo)
#define STAGE_SZ (4 * A_SZ)        // Ahi | Alo | Bhi | Blo = 64 KB
#define SMEM_TOTAL (NSTAGES * STAGE_SZ)   // 192 KB

#define MT (B_DIM / TILE_MM)       // 64
#define NT (NP / TILE_NN)          // 128

// ---- device scratch (globals: no runtime allocation) ----
// Fragment-layout operands:
// A': [rb(512)][kb(256)][lane(32)][reg(4)]  reg r -> X[rb*16+g+8*(r&1)][kb*8+tg+4*(r>>1)]
// B': [nb(2048)][kb(256)][lane(32)][reg(2)] reg r -> W[kb*8+tg+4*r][nb*8+g]
__device__ __align__(256) float g_xhi[(size_t)B_DIM * D_DIM];
__device__ __align__(256) float g_xlo[(size_t)B_DIM * D_DIM];
__device__ __align__(256) float g_whi[(size_t)NP * D_DIM];
__device__ __align__(256) float g_wlo[(size_t)NP * D_DIM];
__device__ __align__(256) float g_p  [(size_t)B_DIM * NP];

// ---------------------------------------------------------------------------
// cvt.rna.tf32.f32 requires a .b32 destination register; result is a valid
// fp32 bit pattern (mantissa rounded to 10 bits), so reinterpret back.
__device__ __forceinline__ float to_tf32(float a) {
    uint32_t r;
    asm("cvt.rna.tf32.f32 %0, %1;" : "=r"(r) : "f"(a));
    return __uint_as_float(r);
}
__device__ __forceinline__ uint32_t smem_u32(const void* p) {
    uint32_t a;
    asm("{ .reg .u64 t; cvta.to.shared.u64 t, %1; cvt.u32.u64 %0, t; }"
        : "=r"(a) : "l"(p));
    return a;
}
__device__ __forceinline__ void cp16(uint32_t sa, const void* g) {
    asm volatile("cp.async.cg.shared.global [%0], [%1], 16;" :: "r"(sa), "l"(g));
}
#define CP_COMMIT() asm volatile("cp.async.commit_group;" ::: "memory")
template<int N> __device__ __forceinline__ void cp_wait() {
    asm volatile("cp.async.wait_group %0;" :: "n"(N) : "memory");
}
__device__ __forceinline__ void lds128(uint32_t* r, uint32_t a) {
    asm volatile("ld.shared.v4.b32 {%0,%1,%2,%3}, [%4];"
                 : "=r"(r[0]), "=r"(r[1]), "=r"(r[2]), "=r"(r[3]) : "r"(a));
}
__device__ __forceinline__ void lds64(uint32_t* r, uint32_t a) {
    asm volatile("ld.shared.v2.b32 {%0,%1}, [%2];"
                 : "=r"(r[0]), "=r"(r[1]) : "r"(a));
}
__device__ __forceinline__ void mma8(float* d, const uint32_t* a, const uint32_t* b) {
    asm volatile(
        "mma.sync.aligned.m16n8k8.row.col.f32.tf32.tf32.f32 "
        "{%0,%1,%2,%3}, {%4,%5,%6,%7}, {%8,%9}, {%0,%1,%2,%3};"
        : "+f"(d[0]), "+f"(d[1]), "+f"(d[2]), "+f"(d[3])
        : "r"(a[0]), "r"(a[1]), "r"(a[2]), "r"(a[3]), "r"(b[0]), "r"(b[1]));
}

// ---------------------------------------------------------------------------
// Prep 1: X -> fragment-layout hi/lo
// ---------------------------------------------------------------------------
__global__ __launch_bounds__(256) void prep_x(const float* __restrict__ x) {
    int idx = blockIdx.x * 256 + threadIdx.x;      // [0, 512*256*32)
    int rb   = idx >> 13;                          // /(256*32)
    int rest = idx & 8191;
    int kb   = rest >> 5;
    int t    = rest & 31;
    int gg   = t >> 2, tg = t & 3;

    int row = rb * 16 + gg;
    int col = kb * 8 + tg;
    float v0 = x[(size_t)row * D_DIM + col];
    float v1 = x[(size_t)(row + 8) * D_DIM + col];
    float v2 = x[(size_t)row * D_DIM + col + 4];
    float v3 = x[(size_t)(row + 8) * D_DIM + col + 4];

    float4 h, l;
    h.x = to_tf32(v0); l.x = v0 - h.x;
    h.y = to_tf32(v1); l.y = v1 - h.y;
    h.z = to_tf32(v2); l.z = v2 - h.z;
    h.w = to_tf32(v3); l.w = v3 - h.w;
    ((float4*)g_xhi)[idx] = h;
    ((float4*)g_xlo)[idx] = l;
}

// ---------------------------------------------------------------------------
// Prep 2: W = [mw^T | rw] (C padded 1000->1024) -> fragment-layout hi/lo
// ---------------------------------------------------------------------------
__device__ __forceinline__ float w_elem(const float* __restrict__ mw,
                                        const float* __restrict__ rw,
                                        int k, int n) {
    if (n < NH) {
        int m = n >> 10, c = n & 1023;
        return (c < C_DIM) ? mw[((size_t)m * D_DIM + k) * C_DIM + c] : 0.0f;
    } else {
        int nn = n - NH;
        int m = nn >> 10, c = nn & 1023;
        return (c < C_DIM) ? rw[(size_t)k * (M_DIM * C_DIM) + m * C_DIM + c] : 0.0f;
    }
}

__global__ __launch_bounds__(256) void prep_w(const float* __restrict__ mw,
                                              const float* __restrict__ rw) {
    int idx = blockIdx.x * 256 + threadIdx.x;      // [0, 2048*256*32)
    int nb   = idx >> 13;
    int rest = idx & 8191;
    int kb   = rest >> 5;
    int t    = rest & 31;
    int gg   = t >> 2, tg = t & 3;

    int n = nb * 8 + gg;
    int k = kb * 8 + tg;
    float v0 = w_elem(mw, rw, k, n);
    float v1 = w_elem(mw, rw, k + 4, n);

    float2 h, l;
    h.x = to_tf32(v0); l.x = v0 - h.x;
    h.y = to_tf32(v1); l.y = v1 - h.y;
    ((float2*)g_whi)[idx] = h;
    ((float2*)g_wlo)[idx] = l;
}

// ---------------------------------------------------------------------------
// Main GEMM: P = X @ W via 3xTF32 mma.sync, 3-stage cp.async pipeline.
// CTA tile 128x128, 8 warps in 4x2 grid, warp tile 32x64.
// ---------------------------------------------------------------------------
__global__ __launch_bounds__(NTHREADS, 1) void gemm_mma() {
    extern __shared__ char smem[];
    const uint32_t sb = smem_u32(smem);
    const int tid  = threadIdx.x;
    const int wid  = tid >> 5, lane = tid & 31;
    const int gg   = lane >> 2, tg = lane & 3;
    const int wm   = wid >> 1, wn = wid & 1;

    // 8x8 CTA supergroups: wave working set ~75MB fits L2.
    const int bid = blockIdx.x;
    const int grp = bid >> 6, r = bid & 63;
    const int gm = grp & 7, gn = grp >> 3;         // 8 x 16 groups
    const int bmt = gm * 8 + (r & 7);              // [0,64)
    const int bnt = gn * 8 + (r >> 3);             // [0,128)
    const int rb_base = bmt * 8;                   // 16-row blocks
    const int nb_base = bnt * 16;                  // 8-col blocks

    const float4* gAh = (const float4*)g_xhi;
    const float4* gAl = (const float4*)g_xlo;
    const float4* gBh = (const float4*)g_whi;
    const float4* gBl = (const float4*)g_wlo;

    auto load_stage = [&](int s, int kk) {
        const uint32_t sa = sb + s * STAGE_SZ;
        const int kb_base = kk * 4;
#pragma unroll
        for (int i = 0; i < 4; i++) {
            int ch = tid + NTHREADS * i;           // [0,1024)
            // A chunk: rb(3b) kb(2b) t(5b), 1 float4 per (rb,kb,t)
            int arb = ch >> 7, akb = (ch >> 5) & 3, at = ch & 31;
            size_t gi = ((size_t)(rb_base + arb) * KB_TOT + kb_base + akb) * 32 + at;
            cp16(sa + ch * 16,            gAh + gi);
            cp16(sa + A_SZ + ch * 16,     gAl + gi);
            // B chunk: nb(4b) kb(2b) j(4b), block = 64 floats = 16 float4
            int bnb = ch >> 6, bkb = (ch >> 4) & 3, bj = ch & 15;
            size_t gj = ((size_t)(nb_base + bnb) * KB_TOT + kb_base + bkb) * 16 + bj;
            cp16(sa + 2 * A_SZ + ch * 16, gBh + gj);
            cp16(sa + 3 * A_SZ + ch * 16, gBl + gj);
        }
    };

    float acc[2][8][4];
#pragma unroll
    for (int i = 0; i < 2; i++)
#pragma unroll
        for (int j = 0; j < 8; j++)
#pragma unroll
            for (int k = 0; k < 4; k++) acc[i][j][k] = 0.0f;

    load_stage(0, 0); CP_COMMIT();
    load_stage(1, 1); CP_COMMIT();

    for (int kk = 0; kk < KITERS; kk++) {
        if (kk + 2 < KITERS) load_stage((kk + 2) % NSTAGES, kk + 2);
        CP_COMMIT();
        cp_wait<2>();
        __syncthreads();

        const uint32_t sa = sb + (kk % NSTAGES) * STAGE_SZ;
#pragma unroll
        for (int kb = 0; kb < 4; kb++) {
            uint32_t ah[2][4], al[2][4];
#pragma unroll
            for (int rr = 0; rr < 2; rr++) {
                int rb = wm * 2 + rr;
                uint32_t off = ((rb * 4 + kb) * 32 + lane) * 16;
                lds128(ah[rr], sa + off);
                lds128(al[rr], sa + A_SZ + off);
            }
#pragma unroll
            for (int nn = 0; nn < 8; nn++) {
                int nb = wn * 8 + nn;
                uint32_t off = ((nb * 4 + kb) * 32 + lane) * 8;
                uint32_t bh[2], bl[2];
                lds64(bh, sa + 2 * A_SZ + off);
                lds64(bl, sa + 3 * A_SZ + off);
#pragma unroll
                for (int rr = 0; rr < 2; rr++) {
                    mma8(acc[rr][nn], ah[rr], bh);   // hi*hi
                    mma8(acc[rr][nn], ah[rr], bl);   // hi*lo
                    mma8(acc[rr][nn], al[rr], bh);   // lo*hi
                }
            }
        }
        __syncthreads();
    }

    // Epilogue: write P tile
    const int bm = bmt * TILE_MM, bn = bnt * TILE_NN;
#pragma unroll
    for (int rr = 0; rr < 2; rr++) {
        int row0 = bm + wm * 32 + rr * 16 + gg;
        float* p0 = g_p + (size_t)row0 * NP;
        float* p1 = g_p + (size_t)(row0 + 8) * NP;
#pragma unroll
        for (int nn = 0; nn < 8; nn++) {
            int col = bn + wn * 64 + nn * 8 + tg * 2;
            *(float2*)(p0 + col) = make_float2(acc[rr][nn][0], acc[rr][nn][1]);
            *(float2*)(p1 + col) = make_float2(acc[rr][nn][2], acc[rr][nn][3]);
        }
    }
}

// ---------------------------------------------------------------------------
// Combine: out[b,c] = sum_m (P[b,m*1024+c]+mb[m,c]) * (P[b,NH+m*1024+c]+rb[m*1000+c])
// ---------------------------------------------------------------------------
__global__ __launch_bounds__(256) void combine(const float* __restrict__ mbias,
                                               const float* __restrict__ rbias,
                                               float* __restrict__ out) {
    int idx = blockIdx.x * 256 + threadIdx.x;
    if (idx >= B_DIM * C_DIM) return;
    int b = idx / C_DIM;
    int c = idx - b * C_DIM;
    const float* p = g_p + (size_t)b * NP;
    float s = 0.0f;
#pragma unroll
    for (int m = 0; m < M_DIM; m++) {
        float o = p[m * 1024 + c]      + mbias[m * C_DIM + c];
        float w = p[NH + m * 1024 + c] + rbias[m * C_DIM + c];
        s = fmaf(o, w, s);
    }
    out[idx] = s;
}

// ---------------------------------------------------------------------------
extern "C" void kernel_launch(void* const* d_in, const int* in_sizes, int n_in,
                              void* d_out, int out_size)
{
    const float* x  = (const float*)d_in[0];   // [8192, 2048]
    const float* mw = (const float*)d_in[1];   // [8, 2048, 1000]
    const float* mb = (const float*)d_in[2];   // [8, 1000]
    const float* rw = (const float*)d_in[3];   // [2048, 8000]
    const float* rb = (const float*)d_in[4];   // [8000]
    float* out = (float*)d_out;                // [8192, 1000]

    cudaFuncSetAttribute(gemm_mma,
        cudaFuncAttributeMaxDynamicSharedMemorySize, SMEM_TOTAL);

    // 1) pack X (hi/lo, fragment layout): 512*256*32 threads
    prep_x<<<(512 * 256 * 32) / 256, 256>>>(x);
    // 2) pack W (transpose+pad+split, fragment layout): 2048*256*32 threads
    prep_w<<<(2048 * 256 * 32) / 256, 256>>>(mw, rw);
    // 3) big GEMM
    gemm_mma<<<MT * NT, NTHREADS, SMEM_TOTAL>>>();
    // 4) bias + product + reduce over m
    combine<<<(B_DIM * C_DIM + 255) / 256, 256>>>(mb, rb, out);
}